// round 14
// baseline (speedup 1.0000x reference)
#include <cuda_runtime.h>
#include <cuda_fp16.h>
#include <stdint.h>
#include <math.h>

#define Tdim 288
#define BT 576
#define NROWS (BT*1024)
#define NELEM ((size_t)NROWS*64)

__device__ float  g_Xp[NELEM];
__device__ __align__(16) __half g_Xph[NELEM];              // fp16 Xp (same layout)
__device__ __align__(16) __half g_S1h[(size_t)BT*65536];   // S1 fp16
__device__ __align__(16) __half g_S2h[(size_t)BT*65536];   // S2 fp16
__device__ float  g_L[1024*1024];       // tf32 An
__device__ __align__(16) __half g_Lh[2048*1024];  // fp16 [An ; An^2]
__device__ __align__(16) __half g_Thh[128*64];    // fp16 folded [Th_S1 ; Th_S2]
__device__ float  g_Thx[64*64];         // tf32 folded Th_Xp
__device__ float  g_dis[1024];
__device__ float  g_v[2][1024];
__device__ float  g_ss[24];
__device__ float  g_lam;
__device__ float  g_temp[Tdim*64];
__device__ float  g_ep[Tdim*64];

__device__ __forceinline__ float blockReduceSum(float v){
    __shared__ float sh[32];
    int lane = threadIdx.x & 31, wid = threadIdx.x >> 5;
    #pragma unroll
    for(int o=16;o;o>>=1) v += __shfl_down_sync(0xffffffffu, v, o);
    if(lane==0) sh[wid]=v;
    __syncthreads();
    int nw = blockDim.x >> 5;
    v = (threadIdx.x < nw) ? sh[threadIdx.x] : 0.f;
    if(wid==0){
        #pragma unroll
        for(int o=16;o;o>>=1) v += __shfl_down_sync(0xffffffffu, v, o);
    }
    return v;
}
__device__ __forceinline__ float tf32r(float f){
    uint32_t r; asm("cvt.rna.tf32.f32 %0, %1;" : "=r"(r) : "f"(f));
    return __uint_as_float(r);
}
__device__ __forceinline__ void threefry(uint32_t k0,uint32_t k1,uint32_t&x0,uint32_t&x1){
    uint32_t ks2 = k0^k1^0x1BD11BDAu;
    x0+=k0; x1+=k1;
    x0+=x1; x1=(x1<<13)|(x1>>19); x1^=x0;
    x0+=x1; x1=(x1<<15)|(x1>>17); x1^=x0;
    x0+=x1; x1=(x1<<26)|(x1>> 6); x1^=x0;
    x0+=x1; x1=(x1<< 6)|(x1>>26); x1^=x0;
    x0+=k1; x1+=ks2+1u;
    x0+=x1; x1=(x1<<17)|(x1>>15); x1^=x0;
    x0+=x1; x1=(x1<<29)|(x1>> 3); x1^=x0;
    x0+=x1; x1=(x1<<16)|(x1>>16); x1^=x0;
    x0+=x1; x1=(x1<<24)|(x1>> 8); x1^=x0;
    x0+=ks2; x1+=k0+2u;
    x0+=x1; x1=(x1<<13)|(x1>>19); x1^=x0;
    x0+=x1; x1=(x1<<15)|(x1>>17); x1^=x0;
    x0+=x1; x1=(x1<<26)|(x1>> 6); x1^=x0;
    x0+=x1; x1=(x1<< 6)|(x1>>26); x1^=x0;
    x0+=k0; x1+=k1+3u;
    x0+=x1; x1=(x1<<17)|(x1>>15); x1^=x0;
    x0+=x1; x1=(x1<<29)|(x1>> 3); x1^=x0;
    x0+=x1; x1=(x1<<16)|(x1>>16); x1^=x0;
    x0+=x1; x1=(x1<<24)|(x1>> 8); x1^=x0;
    x0+=k1; x1+=ks2+4u;
    x0+=x1; x1=(x1<<13)|(x1>>19); x1^=x0;
    x0+=x1; x1=(x1<<15)|(x1>>17); x1^=x0;
    x0+=x1; x1=(x1<<26)|(x1>> 6); x1^=x0;
    x0+=x1; x1=(x1<< 6)|(x1>>26); x1^=x0;
    x0+=ks2; x1+=k0+5u;
}
__device__ float erfinv_f(float x){
    float w = -log1pf(-x*x);
    float p;
    if (w < 5.0f){
        w -= 2.5f;
        p = 2.81022636e-08f;
        p = fmaf(p,w, 3.43273939e-07f);
        p = fmaf(p,w,-3.5233877e-06f);
        p = fmaf(p,w,-4.39150654e-06f);
        p = fmaf(p,w, 0.00021858087f);
        p = fmaf(p,w,-0.00125372503f);
        p = fmaf(p,w,-0.00417768164f);
        p = fmaf(p,w, 0.246640727f);
        p = fmaf(p,w, 1.50140941f);
    } else {
        w = sqrtf(w) - 3.0f;
        p = -0.000200214257f;
        p = fmaf(p,w, 0.000100950558f);
        p = fmaf(p,w, 0.00134934322f);
        p = fmaf(p,w,-0.00367342844f);
        p = fmaf(p,w, 0.00573950773f);
        p = fmaf(p,w,-0.0076224613f);
        p = fmaf(p,w, 0.00943887047f);
        p = fmaf(p,w, 1.00167406f);
        p = fmaf(p,w, 2.83297682f);
    }
    return p*x;
}
__device__ __forceinline__ float bits_to_normal(uint32_t bits){
    float u = __uint_as_float((bits>>9) | 0x3f800000u) - 1.0f;
    const float lo = -0.99999994f;
    float val = u*2.0f + lo;
    val = fmaxf(val, lo);
    return 1.41421354f * erfinv_f(val);
}

// ---------- launch 1: dis + init_v + temp ----------
__global__ void k_pre1(const float* __restrict__ A,
                       const float* __restrict__ eday, const float* __restrict__ eweek,
                       const int* __restrict__ mi, const int* __restrict__ wi){
    int b = blockIdx.x;
    if(b < 1024){
        float s = 0.f;
        const float* row = A + (size_t)b*1024;
        for(int j=threadIdx.x;j<1024;j+=256) s += row[j];
        s = blockReduceSum(s);
        if(threadIdx.x==0) g_dis[b] = rsqrtf(s + 1e-12f);
    } else if(b == 1024){
        if(threadIdx.x < 24) g_ss[threadIdx.x] = 0.f;
        if(threadIdx.x == 0) g_lam = 0.f;
        float loc = 0.f;
        #pragma unroll
        for(int c=0;c<4;c++){
            int i = threadIdx.x*4 + c;
            uint32_t x0 = 0u, x1 = (uint32_t)i;
            threefry(0u, 42u, x0, x1);
            float a = bits_to_normal(x0 ^ x1);
            g_v[0][i] = a;
            loc += a*a;
        }
        float ss = blockReduceSum(loc);
        if(threadIdx.x==0) g_ss[0] = ss;
    } else {
        int t = (b-1025)*4 + (threadIdx.x>>6);
        int d = threadIdx.x & 63;
        int md = ((mi[t] % 288) + 288) % 288;
        int wd = ((wi[t] % 7) + 7) % 7;
        const float factor = (float)(-9.210340371976184/64.0);
        float divv = expf((float)(d & ~1) * factor);
        float ang = (float)t * divv;
        float pe = (d & 1) ? cosf(ang) : sinf(ang);
        g_ep[t*64+d]   = pe;
        g_temp[t*64+d] = eday[md*64+d] + eweek[wd*64+d] + pe;
    }
}

// ---------- launch 2: blocks 0..1023 An prep; blocks 1024.. Xp(+fp16) + X_te ----------
__global__ void k_pre2(const float* __restrict__ A,
                       const float* __restrict__ X, const float* __restrict__ Win,
                       const float* __restrict__ bin, const float* __restrict__ gam,
                       const float* __restrict__ bet, float* __restrict__ out_te){
    __shared__ float Ws[192], bs[64], gs[64], bes[64];
    int tid = threadIdx.x;
    if(blockIdx.x < 1024){
        int i = blockIdx.x;
        float di = g_dis[i];
        for(int j=tid;j<1024;j+=256){
            float v = di * A[(size_t)i*1024+j] * g_dis[j];
            g_L[(size_t)i*1024+j]  = tf32r(v);
            g_Lh[(size_t)i*1024+j] = __float2half(v);
        }
        return;
    }
    if(tid < 192) Ws[tid] = Win[tid];
    else { int d = tid - 192; bs[d]=bin[d]; gs[d]=gam[d]; bes[d]=bet[d]; }
    __syncthreads();
    int r = (blockIdx.x-1024)*8 + (tid>>5);
    int lane = tid & 31;
    int t = (r >> 10) % Tdim;
    const float* xr = X + (size_t)r*3;
    float x0 = xr[0], x1 = xr[1], x2 = xr[2];
    int dA = lane, dB = lane + 32;
    float xpa = fmaf(x2, Ws[128+dA], fmaf(x1, Ws[64+dA], x0*Ws[dA])) + bs[dA];
    float xpb = fmaf(x2, Ws[128+dB], fmaf(x1, Ws[64+dB], x0*Ws[dB])) + bs[dB];
    size_t base = (size_t)r*64;
    g_Xp[base+dA] = xpa;
    g_Xp[base+dB] = xpb;
    g_Xph[base+dA] = __float2half(xpa);
    g_Xph[base+dB] = __float2half(xpb);
    float za = xpa + g_temp[t*64+dA];
    float zb = xpb + g_temp[t*64+dB];
    float s = za+zb, q = za*za + zb*zb;
    #pragma unroll
    for(int o=16;o;o>>=1){ s += __shfl_xor_sync(0xffffffffu,s,o); q += __shfl_xor_sync(0xffffffffu,q,o); }
    float m = s*(1.f/64.f);
    float var = q*(1.f/64.f) - m*m;
    float rs = rsqrtf(var + 1e-5f);
    out_te[base+dA] = (za-m)*rs*gs[dA] + bes[dA];
    out_te[base+dB] = (zb-m)*rs*gs[dB] + bes[dB];
}

// ---------- launch 3: An2 = An@An (tf32), fp16 out rows 1024+ ----------
__global__ void __launch_bounds__(256) k_an2(){
    __shared__ float As[128][20];
    __shared__ float Bs[16][72];
    int m0 = (blockIdx.x&7)*128, n0 = (blockIdx.x>>3)*64;
    int tid = threadIdx.x, warp = tid>>5, lane = tid&31, grp = lane>>2, tig = lane&3;
    int wm = (warp&3)*32, wn = (warp>>2)*32;
    float acc[2][4][4];
    #pragma unroll
    for(int a=0;a<2;a++)
        #pragma unroll
        for(int b=0;b<4;b++)
            #pragma unroll
            for(int c=0;c<4;c++) acc[a][b][c]=0.f;
    for(int k0=0;k0<1024;k0+=16){
        #pragma unroll
        for(int c=0;c<2;c++){
            int q = tid + 256*c; int row = q>>2, kc = (q&3)*4;
            *(float4*)&As[row][kc] = *(const float4*)&g_L[(size_t)(m0+row)*1024 + k0 + kc];
        }
        { int kk = tid>>4, d = (tid&15)*4;
          *(float4*)&Bs[kk][d] = *(const float4*)&g_L[(size_t)(k0+kk)*1024 + n0 + d]; }
        __syncthreads();
        #pragma unroll
        for(int ks=0;ks<2;ks++){
            int kb = ks*8 + tig;
            uint32_t a[2][4], bf[4][2];
            #pragma unroll
            for(int mt=0;mt<2;mt++){
                int m = wm + mt*16 + grp;
                a[mt][0]=__float_as_uint(As[m  ][kb  ]);
                a[mt][1]=__float_as_uint(As[m+8][kb  ]);
                a[mt][2]=__float_as_uint(As[m  ][kb+4]);
                a[mt][3]=__float_as_uint(As[m+8][kb+4]);
            }
            #pragma unroll
            for(int nt=0;nt<4;nt++){
                int n = wn + nt*8 + grp;
                bf[nt][0]=__float_as_uint(Bs[kb  ][n]);
                bf[nt][1]=__float_as_uint(Bs[kb+4][n]);
            }
            #pragma unroll
            for(int mt=0;mt<2;mt++)
                #pragma unroll
                for(int nt=0;nt<4;nt++)
                    asm volatile("mma.sync.aligned.m16n8k8.row.col.f32.tf32.tf32.f32 "
                        "{%0,%1,%2,%3}, {%4,%5,%6,%7}, {%8,%9}, {%0,%1,%2,%3};\n"
                        : "+f"(acc[mt][nt][0]),"+f"(acc[mt][nt][1]),"+f"(acc[mt][nt][2]),"+f"(acc[mt][nt][3])
                        : "r"(a[mt][0]),"r"(a[mt][1]),"r"(a[mt][2]),"r"(a[mt][3]),
                          "r"(bf[nt][0]),"r"(bf[nt][1]));
        }
        __syncthreads();
    }
    #pragma unroll
    for(int mt=0;mt<2;mt++)
        #pragma unroll
        for(int h=0;h<2;h++){
            int r = m0 + wm + mt*16 + grp + 8*h;
            #pragma unroll
            for(int nt=0;nt<4;nt++){
                int c = n0 + wn + nt*8 + 2*tig;
                __half2 hv = __floats2half2_rn(acc[mt][nt][2*h], acc[mt][nt][2*h+1]);
                *(uint32_t*)&g_Lh[(size_t)(1024+r)*1024 + c] = *(uint32_t*)&hv;
            }
        }
}

// ---------- launch 4 (PROFILED): fused S1,S2 = [An;An2] @ Xp (fp16 HMMA) ----------
// 512 thr split into TWO independent 256-thread halves (named barriers 1/2),
// each with its own M-tile (128 rows), own 4-stage A+B cp.async ring.
#define FH_STAGE 18944     // A 10240 + B 8704
#define FH_B     10240
#define FH_HALF  75776     // 4 * FH_STAGE
__global__ void __launch_bounds__(512,1) k_fused(){
    extern __shared__ char sm[];
    uint32_t sb = (uint32_t)__cvta_generic_to_shared(sm);
    int tid = threadIdx.x, warp = tid>>5, lane = tid&31;
    int half = warp>>3, hw = warp&7, ht = tid & 255;
    int grp = lane>>2, tig = lane&3;
    int gm0 = blockIdx.x*256 + half*128;
    const __half* XpB = g_Xph + (size_t)(2*blockIdx.y)*65536;
    int wm = (hw&1)*64, wn = (hw>>1)*32;
    uint32_t hbase = sb + half*FH_HALF;
    uint32_t barid = half + 1;
    float acc[4][4][4];
    #pragma unroll
    for(int a=0;a<4;a++)
        #pragma unroll
        for(int b=0;b<4;b++)
            #pragma unroll
            for(int c=0;c<4;c++) acc[a][b][c]=0.f;

#define ISSUE_H(I) do{ int _i=(I); if(_i<32){ \
    uint32_t st = hbase + (_i&3)*FH_STAGE; \
    _Pragma("unroll") \
    for(int c=0;c<2;c++){ int u = ht + 256*c; int row = u>>2, part = u&3; \
        uint32_t d0 = st + row*80 + part*16; \
        const __half* s0 = g_Lh + (size_t)(gm0+row)*1024 + _i*32 + part*8; \
        asm volatile("cp.async.cg.shared.global [%0], [%1], 16;\n"::"r"(d0),"l"(s0)); } \
    _Pragma("unroll") \
    for(int c=0;c<2;c++){ int v = ht + 256*c; int bk = v>>4, bp = v&15; \
        uint32_t db = st + FH_B + bk*272 + bp*16; \
        const __half* sbp = XpB + (size_t)(bp>>3)*65536 + (size_t)(_i*32+bk)*64 + (bp&7)*8; \
        asm volatile("cp.async.cg.shared.global [%0], [%1], 16;\n"::"r"(db),"l"(sbp)); } } \
    asm volatile("cp.async.commit_group;\n"); }while(0)

    ISSUE_H(0); ISSUE_H(1); ISSUE_H(2);

    for(int i=0;i<32;i++){
        asm volatile("cp.async.wait_group 2;\n");
        asm volatile("bar.sync %0, 256;" :: "r"(barid) : "memory");
        ISSUE_H(i+3);
        uint32_t Au = hbase + (i&3)*FH_STAGE;
        uint32_t Bu = Au + FH_B;
        #pragma unroll
        for(int ks=0;ks<2;ks++){
            uint32_t bf[4][2];
            #pragma unroll
            for(int nt=0;nt<4;nt++){
                uint32_t ad = Bu + (ks*16 + (lane&15))*272 + (wn + nt*8)*2;
                asm volatile("ldmatrix.sync.aligned.m8n8.x2.trans.shared.b16 {%0,%1}, [%2];\n"
                             : "=r"(bf[nt][0]), "=r"(bf[nt][1]) : "r"(ad));
            }
            #pragma unroll
            for(int mt=0;mt<4;mt++){
                uint32_t a0,a1,a2,a3;
                uint32_t ad = Au + (wm + mt*16 + ((lane>>3)&1)*8 + (lane&7))*80
                              + (ks*16 + (lane>>4)*8)*2;
                asm volatile("ldmatrix.sync.aligned.m8n8.x4.shared.b16 {%0,%1,%2,%3}, [%4];\n"
                             : "=r"(a0),"=r"(a1),"=r"(a2),"=r"(a3) : "r"(ad));
                #pragma unroll
                for(int nt=0;nt<4;nt++)
                    asm volatile("mma.sync.aligned.m16n8k16.row.col.f32.f16.f16.f32 "
                        "{%0,%1,%2,%3}, {%4,%5,%6,%7}, {%8,%9}, {%0,%1,%2,%3};\n"
                        : "+f"(acc[mt][nt][0]),"+f"(acc[mt][nt][1]),"+f"(acc[mt][nt][2]),"+f"(acc[mt][nt][3])
                        : "r"(a0),"r"(a1),"r"(a2),"r"(a3),"r"(bf[nt][0]),"r"(bf[nt][1]));
            }
        }
    }
    __half* Sd = (gm0 >= 1024) ? g_S2h : g_S1h;
    #pragma unroll
    for(int mt=0;mt<4;mt++)
        #pragma unroll
        for(int h=0;h<2;h++){
            int node = (gm0 + wm + mt*16 + grp + 8*h) & 1023;
            #pragma unroll
            for(int nt=0;nt<4;nt++){
                int n = wn + nt*8 + 2*tig;
                size_t dst = (size_t)(2*blockIdx.y + (n>>6))*65536 + (size_t)node*64 + (n&63);
                __half2 hv = __floats2half2_rn(acc[mt][nt][2*h], acc[mt][nt][2*h+1]);
                *(uint32_t*)&Sd[dst] = *(uint32_t*)&hv;
            }
        }
#undef ISSUE_H
}

// ---------- matvec chain + theta fold ----------
__global__ void k_matvec(const float* __restrict__ A, int it){
    int row = blockIdx.x*8 + (threadIdx.x>>5);
    int lane = threadIdx.x & 31;
    const float* vin = g_v[(it-1)&1];
    float scale = 1.0f/(sqrtf(g_ss[it-1]) + 1e-12f);
    const float* Ar = A + (size_t)row*1024;
    float s = 0.f;
    #pragma unroll
    for(int j=0;j<32;j++){
        int c = lane + 32*j;
        s += Ar[c]*g_dis[c]*vin[c];
    }
    #pragma unroll
    for(int o=16;o;o>>=1) s += __shfl_down_sync(0xffffffffu, s, o);
    if(lane==0){
        float w = scale*(vin[row] - g_dis[row]*s);
        if(it<=20){ g_v[it&1][row] = w; atomicAdd(&g_ss[it], w*w); }
        else atomicAdd(&g_lam, (vin[row]*scale)*w);
    }
}
__global__ void k_theta(const float* __restrict__ theta){
    float lam = fminf(fmaxf(g_lam,1e-6f),2.0f);
    float c2 = 2.0f/lam, c1 = c2 - 1.0f;
    int idx = threadIdx.x + blockIdx.x*256;
    if(idx < 4096){
        float t0 = theta[idx], t1 = theta[4096+idx], t2 = theta[8192+idx];
        int k = idx>>6, n = idx&63;
        g_Thh[k*64+n]       = __float2half(-c2*t1 - 4.0f*c1*c2*t2);      // Th_S1
        g_Thh[(64+k)*64+n]  = __float2half(2.0f*c2*c2*t2);               // Th_S2
        g_Thx[idx]          = tf32r(t0 + c1*t1 + (2.0f*c1*c1 - 1.0f)*t2);// Th_Xp
    }
}

// ---------- final: combine v2 (fp16 S passes + tf32 Xp pass) + LN ----------
#define CB_TH   0          // ThH fp16: 128 rows stride 144 = 18432
#define CB_TX   18432      // Thx tf32 [64][68] = 17408 -> 35840
#define CB_RING 35840      // 4 x 10240 = 40960 -> 76800
#define CB_ADD  76800
#define CB_G    77056
#define CB_BE   77312      // total 77568
__global__ void __launch_bounds__(256,2) k_combine(const float* __restrict__ cbias,
                    const float* __restrict__ gam, const float* __restrict__ bet,
                    float* __restrict__ out_sp){
    extern __shared__ char sm[];
    uint32_t sb = (uint32_t)__cvta_generic_to_shared(sm);
    float* Tx = (float*)(sm + CB_TX);
    float* sAdd = (float*)(sm + CB_ADD);
    float* sG = (float*)(sm + CB_G);
    float* sBe = (float*)(sm + CB_BE);
    int tid = threadIdx.x, warp = tid>>5, lane = tid&31, grp = lane>>2, tig = lane&3;
    int wm = (warp&3)*32, wn = (warp>>2)*32;
    int row0 = blockIdx.x*128;
    int t = (row0 >> 10) % Tdim;

#define ISSUE_C(I) do{ int _i=(I); if(_i<8){ \
    if(_i<4){ const __half* S = (_i<2)? g_S1h : g_S2h; \
        _Pragma("unroll") \
        for(int c=0;c<2;c++){ int q = tid + 256*c; int row = q>>2, part = q&3; \
            uint32_t d = sb + CB_RING + (_i&3)*10240 + row*80 + part*16; \
            const __half* s = S + (size_t)(row0+row)*64 + (_i&1)*32 + part*8; \
            asm volatile("cp.async.cg.shared.global [%0], [%1], 16;\n"::"r"(d),"l"(s)); } \
    } else { \
        _Pragma("unroll") \
        for(int c=0;c<2;c++){ int q = tid + 256*c; int row = q>>2, part = q&3; \
            uint32_t d = sb + CB_RING + (_i&3)*10240 + row*80 + part*16; \
            const float* s = g_Xp + (size_t)(row0+row)*64 + (_i&3)*16 + part*4; \
            asm volatile("cp.async.cg.shared.global [%0], [%1], 16;\n"::"r"(d),"l"(s)); } } } \
    asm volatile("cp.async.commit_group;\n"); }while(0)

    ISSUE_C(0); ISSUE_C(1); ISSUE_C(2);
    #pragma unroll
    for(int c=0;c<16;c++){
        int w = tid + 256*c;
        int k = w>>5, col2 = w&31;
        *(uint32_t*)(sm + CB_TH + k*144 + col2*4) = ((const uint32_t*)g_Thh)[w];
    }
    #pragma unroll
    for(int c=0;c<4;c++){
        int q = tid + 256*c; int k = q>>4, n = (q&15)*4;
        *(float4*)&Tx[k*68+n] = *(const float4*)&g_Thx[k*64+n];
    }
    if(tid < 64){
        sAdd[tid] = cbias[tid] + g_ep[t*64+tid];
        sG[tid] = gam[tid]; sBe[tid] = bet[tid];
    }
    float acc[2][4][4];
    #pragma unroll
    for(int a=0;a<2;a++)
        #pragma unroll
        for(int b=0;b<4;b++)
            #pragma unroll
            for(int c=0;c<4;c++) acc[a][b][c]=0.f;

    for(int i=0;i<8;i++){
        asm volatile("cp.async.wait_group 2;\n");
        __syncthreads();
        ISSUE_C(i+3);
        uint32_t Au = sb + CB_RING + (i&3)*10240;
        if(i<4){
            #pragma unroll
            for(int ks=0;ks<2;ks++){
                uint32_t bf[4][2];
                #pragma unroll
                for(int nt=0;nt<4;nt++){
                    uint32_t ad = sb + CB_TH + (i*32 + ks*16 + (lane&15))*144 + (wn + nt*8)*2;
                    asm volatile("ldmatrix.sync.aligned.m8n8.x2.trans.shared.b16 {%0,%1}, [%2];\n"
                                 : "=r"(bf[nt][0]), "=r"(bf[nt][1]) : "r"(ad));
                }
                #pragma unroll
                for(int mt=0;mt<2;mt++){
                    uint32_t a0,a1,a2,a3;
                    uint32_t ad = Au + (wm + mt*16 + ((lane>>3)&1)*8 + (lane&7))*80
                                  + (ks*16 + (lane>>4)*8)*2;
                    asm volatile("ldmatrix.sync.aligned.m8n8.x4.shared.b16 {%0,%1,%2,%3}, [%4];\n"
                                 : "=r"(a0),"=r"(a1),"=r"(a2),"=r"(a3) : "r"(ad));
                    #pragma unroll
                    for(int nt=0;nt<4;nt++)
                        asm volatile("mma.sync.aligned.m16n8k16.row.col.f32.f16.f16.f32 "
                            "{%0,%1,%2,%3}, {%4,%5,%6,%7}, {%8,%9}, {%0,%1,%2,%3};\n"
                            : "+f"(acc[mt][nt][0]),"+f"(acc[mt][nt][1]),"+f"(acc[mt][nt][2]),"+f"(acc[mt][nt][3])
                            : "r"(a0),"r"(a1),"r"(a2),"r"(a3),"r"(bf[nt][0]),"r"(bf[nt][1]));
                }
            }
        } else {
            float* As = (float*)(sm + CB_RING + (i&3)*10240);
            #pragma unroll
            for(int ks=0;ks<2;ks++){
                int kb = ks*8 + tig;
                uint32_t a[2][4], bf[4][2];
                #pragma unroll
                for(int mt=0;mt<2;mt++){
                    int m = wm + mt*16 + grp;
                    a[mt][0]=__float_as_uint(tf32r(As[m*20+kb]));
                    a[mt][1]=__float_as_uint(tf32r(As[(m+8)*20+kb]));
                    a[mt][2]=__float_as_uint(tf32r(As[m*20+kb+4]));
                    a[mt][3]=__float_as_uint(tf32r(As[(m+8)*20+kb+4]));
                }
                #pragma unroll
                for(int nt=0;nt<4;nt++){
                    int n = wn + nt*8 + grp;
                    bf[nt][0]=__float_as_uint(Tx[((i-4)*16+kb)*68+n]);
                    bf[nt][1]=__float_as_uint(Tx[((i-4)*16+kb+4)*68+n]);
                }
                #pragma unroll
                for(int mt=0;mt<2;mt++)
                    #pragma unroll
                    for(int nt=0;nt<4;nt++)
                        asm volatile("mma.sync.aligned.m16n8k8.row.col.f32.tf32.tf32.f32 "
                            "{%0,%1,%2,%3}, {%4,%5,%6,%7}, {%8,%9}, {%0,%1,%2,%3};\n"
                            : "+f"(acc[mt][nt][0]),"+f"(acc[mt][nt][1]),"+f"(acc[mt][nt][2]),"+f"(acc[mt][nt][3])
                            : "r"(a[mt][0]),"r"(a[mt][1]),"r"(a[mt][2]),"r"(a[mt][3]),
                              "r"(bf[nt][0]),"r"(bf[nt][1]));
            }
        }
    }
    asm volatile("cp.async.wait_group 0;\n");
    __syncthreads();
    float* Z = (float*)sm;
    #pragma unroll
    for(int mt=0;mt<2;mt++)
        #pragma unroll
        for(int h=0;h<2;h++){
            int rloc = wm + mt*16 + grp + 8*h;
            #pragma unroll
            for(int nt=0;nt<4;nt++){
                int c = wn + nt*8 + 2*tig;
                float* Ax = (float*)(sm + CB_RING + (c>>4)*10240);
                float xx = Ax[rloc*20 + (c&15)];
                float xy = Ax[rloc*20 + (c&15) + 1];
                Z[rloc*68+c]   = acc[mt][nt][2*h]   + xx + sAdd[c];
                Z[rloc*68+c+1] = acc[mt][nt][2*h+1] + xy + sAdd[c+1];
            }
        }
    __syncthreads();
    #pragma unroll
    for(int it=0;it<8;it++){
        int r = (tid>>4) + 16*it;
        int cb = (tid&15)*4;
        float4 z = *(float4*)&Z[r*68 + cb];
        float s = z.x+z.y+z.z+z.w;
        float q = z.x*z.x+z.y*z.y+z.z*z.z+z.w*z.w;
        #pragma unroll
        for(int o=8;o;o>>=1){ s += __shfl_xor_sync(0xffffffffu,s,o); q += __shfl_xor_sync(0xffffffffu,q,o); }
        float m = s*(1.f/64.f);
        float rs = rsqrtf(q*(1.f/64.f) - m*m + 1e-5f);
        float4 o;
        o.x = (z.x-m)*rs*sG[cb]   + sBe[cb];
        o.y = (z.y-m)*rs*sG[cb+1] + sBe[cb+1];
        o.z = (z.z-m)*rs*sG[cb+2] + sBe[cb+2];
        o.w = (z.w-m)*rs*sG[cb+3] + sBe[cb+3];
        *(float4*)&out_sp[(size_t)(row0+r)*64 + cb] = o;
    }
#undef ISSUE_C
}

// ---------- launch ----------
extern "C" void kernel_launch(void* const* d_in, const int* in_sizes, int n_in,
                              void* d_out, int out_size){
    const float* X     = (const float*)d_in[0];
    const float* A     = (const float*)d_in[1];
    const float* Win   = (const float*)d_in[2];
    const float* bin   = (const float*)d_in[3];
    const float* theta = (const float*)d_in[4];
    const float* cbias = (const float*)d_in[5];
    const float* eday  = (const float*)d_in[6];
    const float* eweek = (const float*)d_in[7];
    const float* gam   = (const float*)d_in[8];
    const float* bet   = (const float*)d_in[9];
    const int*   mi    = (const int*)d_in[10];
    const int*   wi    = (const int*)d_in[11];
    float* out = (float*)d_out;

    cudaFuncSetAttribute(k_fused,   cudaFuncAttributeMaxDynamicSharedMemorySize, 2*FH_HALF);
    cudaFuncSetAttribute(k_combine, cudaFuncAttributeMaxDynamicSharedMemorySize, 77568);

    k_pre1<<<1097,256>>>(A, eday, eweek, mi, wi);
    k_pre2<<<1024 + NROWS/8,256>>>(A, X, Win, bin, gam, bet, out);
    k_an2<<<128,256>>>();
    k_fused<<<dim3(8,288),512,2*FH_HALF>>>();                // 4th launch -> profiled
    for(int it=1; it<=21; ++it)
        k_matvec<<<128,256>>>(A, it);
    k_theta<<<16,256>>>(theta);
    k_combine<<<NROWS/128,256,77568>>>(cbias, gam, bet, out + NELEM);
}

// round 15
// speedup vs baseline: 1.0501x; 1.0501x over previous
#include <cuda_runtime.h>
#include <cuda_fp16.h>
#include <stdint.h>
#include <math.h>

#define Tdim 288
#define BT 576
#define NROWS (BT*1024)
#define NELEM ((size_t)NROWS*64)

__device__ float  g_Xp[NELEM];
__device__ __align__(16) __half g_Xph[NELEM];
__device__ float  g_L[1024*1024];                 // tf32 An
__device__ __align__(16) __half g_Lh[2048*1024];  // fp16 [An ; An^2]
__device__ float  g_dis[1024];
__device__ float  g_v[2][1024];
__device__ float  g_ss[24];
__device__ float  g_lam;
__device__ float  g_temp[Tdim*64];
__device__ float  g_ep[Tdim*64];

__device__ __forceinline__ float blockReduceSum(float v){
    __shared__ float sh[32];
    int lane = threadIdx.x & 31, wid = threadIdx.x >> 5;
    #pragma unroll
    for(int o=16;o;o>>=1) v += __shfl_down_sync(0xffffffffu, v, o);
    if(lane==0) sh[wid]=v;
    __syncthreads();
    int nw = blockDim.x >> 5;
    v = (threadIdx.x < nw) ? sh[threadIdx.x] : 0.f;
    if(wid==0){
        #pragma unroll
        for(int o=16;o;o>>=1) v += __shfl_down_sync(0xffffffffu, v, o);
    }
    return v;
}
__device__ __forceinline__ float tf32r(float f){
    uint32_t r; asm("cvt.rna.tf32.f32 %0, %1;" : "=r"(r) : "f"(f));
    return __uint_as_float(r);
}
__device__ __forceinline__ void threefry(uint32_t k0,uint32_t k1,uint32_t&x0,uint32_t&x1){
    uint32_t ks2 = k0^k1^0x1BD11BDAu;
    x0+=k0; x1+=k1;
    x0+=x1; x1=(x1<<13)|(x1>>19); x1^=x0;
    x0+=x1; x1=(x1<<15)|(x1>>17); x1^=x0;
    x0+=x1; x1=(x1<<26)|(x1>> 6); x1^=x0;
    x0+=x1; x1=(x1<< 6)|(x1>>26); x1^=x0;
    x0+=k1; x1+=ks2+1u;
    x0+=x1; x1=(x1<<17)|(x1>>15); x1^=x0;
    x0+=x1; x1=(x1<<29)|(x1>> 3); x1^=x0;
    x0+=x1; x1=(x1<<16)|(x1>>16); x1^=x0;
    x0+=x1; x1=(x1<<24)|(x1>> 8); x1^=x0;
    x0+=ks2; x1+=k0+2u;
    x0+=x1; x1=(x1<<13)|(x1>>19); x1^=x0;
    x0+=x1; x1=(x1<<15)|(x1>>17); x1^=x0;
    x0+=x1; x1=(x1<<26)|(x1>> 6); x1^=x0;
    x0+=x1; x1=(x1<< 6)|(x1>>26); x1^=x0;
    x0+=k0; x1+=k1+3u;
    x0+=x1; x1=(x1<<17)|(x1>>15); x1^=x0;
    x0+=x1; x1=(x1<<29)|(x1>> 3); x1^=x0;
    x0+=x1; x1=(x1<<16)|(x1>>16); x1^=x0;
    x0+=x1; x1=(x1<<24)|(x1>> 8); x1^=x0;
    x0+=k1; x1+=ks2+4u;
    x0+=x1; x1=(x1<<13)|(x1>>19); x1^=x0;
    x0+=x1; x1=(x1<<15)|(x1>>17); x1^=x0;
    x0+=x1; x1=(x1<<26)|(x1>> 6); x1^=x0;
    x0+=x1; x1=(x1<< 6)|(x1>>26); x1^=x0;
    x0+=ks2; x1+=k0+5u;
}
__device__ float erfinv_f(float x){
    float w = -log1pf(-x*x);
    float p;
    if (w < 5.0f){
        w -= 2.5f;
        p = 2.81022636e-08f;
        p = fmaf(p,w, 3.43273939e-07f);
        p = fmaf(p,w,-3.5233877e-06f);
        p = fmaf(p,w,-4.39150654e-06f);
        p = fmaf(p,w, 0.00021858087f);
        p = fmaf(p,w,-0.00125372503f);
        p = fmaf(p,w,-0.00417768164f);
        p = fmaf(p,w, 0.246640727f);
        p = fmaf(p,w, 1.50140941f);
    } else {
        w = sqrtf(w) - 3.0f;
        p = -0.000200214257f;
        p = fmaf(p,w, 0.000100950558f);
        p = fmaf(p,w, 0.00134934322f);
        p = fmaf(p,w,-0.00367342844f);
        p = fmaf(p,w, 0.00573950773f);
        p = fmaf(p,w,-0.0076224613f);
        p = fmaf(p,w, 0.00943887047f);
        p = fmaf(p,w, 1.00167406f);
        p = fmaf(p,w, 2.83297682f);
    }
    return p*x;
}
__device__ __forceinline__ float bits_to_normal(uint32_t bits){
    float u = __uint_as_float((bits>>9) | 0x3f800000u) - 1.0f;
    const float lo = -0.99999994f;
    float val = u*2.0f + lo;
    val = fmaxf(val, lo);
    return 1.41421354f * erfinv_f(val);
}

// ---------- launch 1: dis + init_v + temp ----------
__global__ void k_pre1(const float* __restrict__ A,
                       const float* __restrict__ eday, const float* __restrict__ eweek,
                       const int* __restrict__ mi, const int* __restrict__ wi){
    int b = blockIdx.x;
    if(b < 1024){
        float s = 0.f;
        const float* row = A + (size_t)b*1024;
        for(int j=threadIdx.x;j<1024;j+=256) s += row[j];
        s = blockReduceSum(s);
        if(threadIdx.x==0) g_dis[b] = rsqrtf(s + 1e-12f);
    } else if(b == 1024){
        if(threadIdx.x < 24) g_ss[threadIdx.x] = 0.f;
        if(threadIdx.x == 0) g_lam = 0.f;
        float loc = 0.f;
        #pragma unroll
        for(int c=0;c<4;c++){
            int i = threadIdx.x*4 + c;
            uint32_t x0 = 0u, x1 = (uint32_t)i;
            threefry(0u, 42u, x0, x1);
            float a = bits_to_normal(x0 ^ x1);
            g_v[0][i] = a;
            loc += a*a;
        }
        float ss = blockReduceSum(loc);
        if(threadIdx.x==0) g_ss[0] = ss;
    } else {
        int t = (b-1025)*4 + (threadIdx.x>>6);
        int d = threadIdx.x & 63;
        int md = ((mi[t] % 288) + 288) % 288;
        int wd = ((wi[t] % 7) + 7) % 7;
        const float factor = (float)(-9.210340371976184/64.0);
        float divv = expf((float)(d & ~1) * factor);
        float ang = (float)t * divv;
        float pe = (d & 1) ? cosf(ang) : sinf(ang);
        g_ep[t*64+d]   = pe;
        g_temp[t*64+d] = eday[md*64+d] + eweek[wd*64+d] + pe;
    }
}

// ---------- launch 2: blocks 0..1023 An prep; blocks 1024.. Xp(+fp16) + X_te ----------
__global__ void k_pre2(const float* __restrict__ A,
                       const float* __restrict__ X, const float* __restrict__ Win,
                       const float* __restrict__ bin, const float* __restrict__ gam,
                       const float* __restrict__ bet, float* __restrict__ out_te){
    __shared__ float Ws[192], bs[64], gs[64], bes[64];
    int tid = threadIdx.x;
    if(blockIdx.x < 1024){
        int i = blockIdx.x;
        float di = g_dis[i];
        for(int j=tid;j<1024;j+=256){
            float v = di * A[(size_t)i*1024+j] * g_dis[j];
            g_L[(size_t)i*1024+j]  = tf32r(v);
            g_Lh[(size_t)i*1024+j] = __float2half(v);
        }
        return;
    }
    if(tid < 192) Ws[tid] = Win[tid];
    else { int d = tid - 192; bs[d]=bin[d]; gs[d]=gam[d]; bes[d]=bet[d]; }
    __syncthreads();
    int r = (blockIdx.x-1024)*8 + (tid>>5);
    int lane = tid & 31;
    int t = (r >> 10) % Tdim;
    const float* xr = X + (size_t)r*3;
    float x0 = xr[0], x1 = xr[1], x2 = xr[2];
    int dA = lane, dB = lane + 32;
    float xpa = fmaf(x2, Ws[128+dA], fmaf(x1, Ws[64+dA], x0*Ws[dA])) + bs[dA];
    float xpb = fmaf(x2, Ws[128+dB], fmaf(x1, Ws[64+dB], x0*Ws[dB])) + bs[dB];
    size_t base = (size_t)r*64;
    g_Xp[base+dA] = xpa;
    g_Xp[base+dB] = xpb;
    g_Xph[base+dA] = __float2half(xpa);
    g_Xph[base+dB] = __float2half(xpb);
    float za = xpa + g_temp[t*64+dA];
    float zb = xpb + g_temp[t*64+dB];
    float s = za+zb, q = za*za + zb*zb;
    #pragma unroll
    for(int o=16;o;o>>=1){ s += __shfl_xor_sync(0xffffffffu,s,o); q += __shfl_xor_sync(0xffffffffu,q,o); }
    float m = s*(1.f/64.f);
    float var = q*(1.f/64.f) - m*m;
    float rs = rsqrtf(var + 1e-5f);
    out_te[base+dA] = (za-m)*rs*gs[dA] + bes[dA];
    out_te[base+dB] = (zb-m)*rs*gs[dB] + bes[dB];
}

// ---------- launch 3: An2 = An@An (tf32), fp16 out rows 1024+ ----------
__global__ void __launch_bounds__(256) k_an2(){
    __shared__ float As[128][20];
    __shared__ float Bs[16][72];
    int m0 = (blockIdx.x&7)*128, n0 = (blockIdx.x>>3)*64;
    int tid = threadIdx.x, warp = tid>>5, lane = tid&31, grp = lane>>2, tig = lane&3;
    int wm = (warp&3)*32, wn = (warp>>2)*32;
    float acc[2][4][4];
    #pragma unroll
    for(int a=0;a<2;a++)
        #pragma unroll
        for(int b=0;b<4;b++)
            #pragma unroll
            for(int c=0;c<4;c++) acc[a][b][c]=0.f;
    for(int k0=0;k0<1024;k0+=16){
        #pragma unroll
        for(int c=0;c<2;c++){
            int q = tid + 256*c; int row = q>>2, kc = (q&3)*4;
            *(float4*)&As[row][kc] = *(const float4*)&g_L[(size_t)(m0+row)*1024 + k0 + kc];
        }
        { int kk = tid>>4, d = (tid&15)*4;
          *(float4*)&Bs[kk][d] = *(const float4*)&g_L[(size_t)(k0+kk)*1024 + n0 + d]; }
        __syncthreads();
        #pragma unroll
        for(int ks=0;ks<2;ks++){
            int kb = ks*8 + tig;
            uint32_t a[2][4], bf[4][2];
            #pragma unroll
            for(int mt=0;mt<2;mt++){
                int m = wm + mt*16 + grp;
                a[mt][0]=__float_as_uint(As[m  ][kb  ]);
                a[mt][1]=__float_as_uint(As[m+8][kb  ]);
                a[mt][2]=__float_as_uint(As[m  ][kb+4]);
                a[mt][3]=__float_as_uint(As[m+8][kb+4]);
            }
            #pragma unroll
            for(int nt=0;nt<4;nt++){
                int n = wn + nt*8 + grp;
                bf[nt][0]=__float_as_uint(Bs[kb  ][n]);
                bf[nt][1]=__float_as_uint(Bs[kb+4][n]);
            }
            #pragma unroll
            for(int mt=0;mt<2;mt++)
                #pragma unroll
                for(int nt=0;nt<4;nt++)
                    asm volatile("mma.sync.aligned.m16n8k8.row.col.f32.tf32.tf32.f32 "
                        "{%0,%1,%2,%3}, {%4,%5,%6,%7}, {%8,%9}, {%0,%1,%2,%3};\n"
                        : "+f"(acc[mt][nt][0]),"+f"(acc[mt][nt][1]),"+f"(acc[mt][nt][2]),"+f"(acc[mt][nt][3])
                        : "r"(a[mt][0]),"r"(a[mt][1]),"r"(a[mt][2]),"r"(a[mt][3]),
                          "r"(bf[nt][0]),"r"(bf[nt][1]));
        }
        __syncthreads();
    }
    #pragma unroll
    for(int mt=0;mt<2;mt++)
        #pragma unroll
        for(int h=0;h<2;h++){
            int r = m0 + wm + mt*16 + grp + 8*h;
            #pragma unroll
            for(int nt=0;nt<4;nt++){
                int c = n0 + wn + nt*8 + 2*tig;
                __half2 hv = __floats2half2_rn(acc[mt][nt][2*h], acc[mt][nt][2*h+1]);
                *(uint32_t*)&g_Lh[(size_t)(1024+r)*1024 + c] = *(uint32_t*)&hv;
            }
        }
}

// ---------- matvec chain (must run BEFORE k_fused: provides g_lam) ----------
__global__ void k_matvec(const float* __restrict__ A, int it){
    int row = blockIdx.x*8 + (threadIdx.x>>5);
    int lane = threadIdx.x & 31;
    const float* vin = g_v[(it-1)&1];
    float scale = 1.0f/(sqrtf(g_ss[it-1]) + 1e-12f);
    const float* Ar = A + (size_t)row*1024;
    float s = 0.f;
    #pragma unroll
    for(int j=0;j<32;j++){
        int c = lane + 32*j;
        s += Ar[c]*g_dis[c]*vin[c];
    }
    #pragma unroll
    for(int o=16;o;o>>=1) s += __shfl_down_sync(0xffffffffu, s, o);
    if(lane==0){
        float w = scale*(vin[row] - g_dis[row]*s);
        if(it<=20){ g_v[it&1][row] = w; atomicAdd(&g_ss[it], w*w); }
        else atomicAdd(&g_lam, (vin[row]*scale)*w);
    }
}

// ---------- k_fused: S1,S2 mainloop + theta-combine + LN, all fused ----------
// 512 thr, 1 CTA/SM. Mainloop = R13 (M=256 stacked: An[bx*128..+128) ; An2[same]).
// Epilogue: Sep fp16 -> out_s = Sep@[Th1;Th2] (fp16) + Xp@Thx (tf32) -> +Xp+add -> LN -> out_sp.
#define FS_STG 29184       // ring stage: A 20480 + B 8704 (x4 = 116736)
#define FS_BO  20480
#define EP_SEP 0           // 2 x 128 x 272B = 69632
#define EP_XPS 69632       // 2 x 128 x 272B = 69632 -> 139264
#define EP_THS 139264      // 128 x 144B = 18432 -> 157696
#define EP_THX 157696      // 64 x 272B = 17408 -> 175104
#define EP_ADD 175104      // 2 x 64 x 4 = 512
#define EP_G   175616      // 256
#define EP_BE  175872      // 256 -> 176128
#define FS_SMEM 176128
__global__ void __launch_bounds__(512,1) k_fused(const float* __restrict__ theta,
                    const float* __restrict__ cbias, const float* __restrict__ gam,
                    const float* __restrict__ bet, float* __restrict__ out_sp){
    extern __shared__ char sm[];
    uint32_t sb = (uint32_t)__cvta_generic_to_shared(sm);
    int tid = threadIdx.x, warp = tid>>5, lane = tid&31;
    int grp = lane>>2, tig = lane&3;
    int bx = blockIdx.x, by = blockIdx.y;
    int gm0 = bx*128;
    const __half* XpB = g_Xph + (size_t)(2*by)*65536;
    int wm = (warp&3)*64, wn = (warp>>2)*32;

    // ---- inline theta fold + add/gamma/beta (regions untouched by ring) ----
    {
        float lam = fminf(fmaxf(g_lam,1e-6f),2.0f);
        float c2 = 2.0f/lam, c1 = c2 - 1.0f;
        #pragma unroll
        for(int c=0;c<8;c++){
            int idx = tid + 512*c;
            float t0 = theta[idx], t1 = theta[4096+idx], t2 = theta[8192+idx];
            int k = idx>>6, o = idx&63;
            *(__half*)(sm + EP_THS + k*144 + o*2)      = __float2half(-c2*t1 - 4.0f*c1*c2*t2);
            *(__half*)(sm + EP_THS + (64+k)*144 + o*2) = __float2half(2.0f*c2*c2*t2);
            *(float*)(sm + EP_THX + k*272 + o*4)       = tf32r(t0 + c1*t1 + (2.0f*c1*c1 - 1.0f)*t2);
        }
        if(tid < 128){
            int b = tid>>6, o = tid&63;
            ((float*)(sm+EP_ADD))[tid] = cbias[o] + g_ep[((2*by+b)%Tdim)*64 + o];
        }
        if(tid < 64){
            ((float*)(sm+EP_G))[tid]  = gam[tid];
            ((float*)(sm+EP_BE))[tid] = bet[tid];
        }
    }

    float acc[4][4][4];
    #pragma unroll
    for(int a=0;a<4;a++)
        #pragma unroll
        for(int b=0;b<4;b++)
            #pragma unroll
            for(int c=0;c<4;c++) acc[a][b][c]=0.f;

    int a_row = tid>>2, a_part = tid&3;
    int b_k = tid>>4, b_part = tid&15;
    size_t b_src_off = (size_t)(b_part>>3)*65536 + (size_t)b_k*64 + (b_part&7)*8;

#define ISSUE_AB(I) do{ int _i=(I); if(_i<32){ \
    uint32_t st = sb + (_i&3)*FS_STG; \
    uint32_t d0 = st + a_row*80 + a_part*16; \
    const __half* s0 = g_Lh + (size_t)(gm0+a_row)*1024 + _i*32 + a_part*8; \
    asm volatile("cp.async.cg.shared.global [%0], [%1], 16;\n"::"r"(d0),"l"(s0)); \
    const __half* s1 = g_Lh + (size_t)(1024+gm0+a_row)*1024 + _i*32 + a_part*8; \
    asm volatile("cp.async.cg.shared.global [%0], [%1], 16;\n"::"r"(d0+128*80),"l"(s1)); \
    uint32_t db = st + FS_BO + b_k*272 + b_part*16; \
    const __half* sbp = XpB + b_src_off + (size_t)(_i*32)*64; \
    asm volatile("cp.async.cg.shared.global [%0], [%1], 16;\n"::"r"(db),"l"(sbp)); } \
    asm volatile("cp.async.commit_group;\n"); }while(0)

    ISSUE_AB(0); ISSUE_AB(1); ISSUE_AB(2);

    for(int i=0;i<32;i++){
        asm volatile("cp.async.wait_group 2;\n");
        __syncthreads();
        ISSUE_AB(i+3);
        uint32_t Au = sb + (i&3)*FS_STG;
        uint32_t Bu = Au + FS_BO;
        #pragma unroll
        for(int ks=0;ks<2;ks++){
            uint32_t bf[4][2];
            #pragma unroll
            for(int nt=0;nt<4;nt++){
                uint32_t ad = Bu + (ks*16 + (lane&15))*272 + (wn + nt*8)*2;
                asm volatile("ldmatrix.sync.aligned.m8n8.x2.trans.shared.b16 {%0,%1}, [%2];\n"
                             : "=r"(bf[nt][0]), "=r"(bf[nt][1]) : "r"(ad));
            }
            #pragma unroll
            for(int mt=0;mt<4;mt++){
                uint32_t a0,a1,a2,a3;
                uint32_t ad = Au + (wm + mt*16 + ((lane>>3)&1)*8 + (lane&7))*80
                              + (ks*16 + (lane>>4)*8)*2;
                asm volatile("ldmatrix.sync.aligned.m8n8.x4.shared.b16 {%0,%1,%2,%3}, [%4];\n"
                             : "=r"(a0),"=r"(a1),"=r"(a2),"=r"(a3) : "r"(ad));
                #pragma unroll
                for(int nt=0;nt<4;nt++)
                    asm volatile("mma.sync.aligned.m16n8k16.row.col.f32.f16.f16.f32 "
                        "{%0,%1,%2,%3}, {%4,%5,%6,%7}, {%8,%9}, {%0,%1,%2,%3};\n"
                        : "+f"(acc[mt][nt][0]),"+f"(acc[mt][nt][1]),"+f"(acc[mt][nt][2]),"+f"(acc[mt][nt][3])
                        : "r"(a0),"r"(a1),"r"(a2),"r"(a3),"r"(bf[nt][0]),"r"(bf[nt][1]));
            }
        }
    }
    asm volatile("cp.async.wait_group 0;\n");
    __syncthreads();                       // ring dead; Sep/XpS regions reusable

    // ---- store acc -> Sep fp16 [b][node][k0..127] (stride 272B) ----
    #pragma unroll
    for(int mt=0;mt<4;mt++)
        #pragma unroll
        for(int h=0;h<2;h++){
            int r = wm + mt*16 + grp + 8*h;       // stacked 0..255
            int nl = r & 127, sb2 = r >> 7;
            #pragma unroll
            for(int nt=0;nt<4;nt++){
                int c = wn + nt*8 + 2*tig;
                int b = c >> 6, k = sb2*64 + (c & 63);
                __half2 hv = __floats2half2_rn(acc[mt][nt][2*h], acc[mt][nt][2*h+1]);
                *(uint32_t*)(sm + EP_SEP + b*34816 + nl*272 + k*2) = *(uint32_t*)&hv;
            }
        }
    // ---- load Xp tiles (both b) into XpS (stride 68 floats) ----
    #pragma unroll
    for(int c=0;c<8;c++){
        int idx = tid + 512*c;                // 4096 x 16B
        int row = idx>>4, part = idx&15;      // row 0..255 (b*128+nl)
        uint32_t d = sb + EP_XPS + row*272 + part*16;
        const float* s = g_Xp + ((size_t)(2*by + (row>>7))*1024 + gm0 + (row&127))*64 + part*4;
        asm volatile("cp.async.cg.shared.global [%0], [%1], 16;\n"::"r"(d),"l"(s));
    }
    asm volatile("cp.async.commit_group;\ncp.async.wait_group 0;\n");
    __syncthreads();

    // ---- epilogue GEMMs: half = b ----
    int half = warp>>3, hw = warp&7;
    int wm2 = (hw&3)*32, wn2 = (hw>>2)*32;
    uint32_t SepB = sb + EP_SEP + half*34816;
    float* Xf  = (float*)(sm + EP_XPS) + half*128*68;
    float* Thx = (float*)(sm + EP_THX);
    float acc2[2][4][4];
    #pragma unroll
    for(int a=0;a<2;a++)
        #pragma unroll
        for(int b=0;b<4;b++)
            #pragma unroll
            for(int c=0;c<4;c++) acc2[a][b][c]=0.f;

    #pragma unroll
    for(int ks=0;ks<8;ks++){                 // fp16, K=128
        uint32_t bf[4][2];
        #pragma unroll
        for(int nt=0;nt<4;nt++){
            uint32_t ad = sb + EP_THS + (ks*16 + (lane&15))*144 + (wn2 + nt*8)*2;
            asm volatile("ldmatrix.sync.aligned.m8n8.x2.trans.shared.b16 {%0,%1}, [%2];\n"
                         : "=r"(bf[nt][0]), "=r"(bf[nt][1]) : "r"(ad));
        }
        #pragma unroll
        for(int mt=0;mt<2;mt++){
            uint32_t a0,a1,a2,a3;
            uint32_t ad = SepB + (wm2 + mt*16 + ((lane>>3)&1)*8 + (lane&7))*272
                          + (ks*16 + (lane>>4)*8)*2;
            asm volatile("ldmatrix.sync.aligned.m8n8.x4.shared.b16 {%0,%1,%2,%3}, [%4];\n"
                         : "=r"(a0),"=r"(a1),"=r"(a2),"=r"(a3) : "r"(ad));
            #pragma unroll
            for(int nt=0;nt<4;nt++)
                asm volatile("mma.sync.aligned.m16n8k16.row.col.f32.f16.f16.f32 "
                    "{%0,%1,%2,%3}, {%4,%5,%6,%7}, {%8,%9}, {%0,%1,%2,%3};\n"
                    : "+f"(acc2[mt][nt][0]),"+f"(acc2[mt][nt][1]),"+f"(acc2[mt][nt][2]),"+f"(acc2[mt][nt][3])
                    : "r"(a0),"r"(a1),"r"(a2),"r"(a3),"r"(bf[nt][0]),"r"(bf[nt][1]));
        }
    }
    #pragma unroll
    for(int ks=0;ks<8;ks++){                 // tf32 Xp@Thx, K=64
        int kb = ks*8 + tig;
        uint32_t a[2][4], bf[4][2];
        #pragma unroll
        for(int mt=0;mt<2;mt++){
            int m = wm2 + mt*16 + grp;
            a[mt][0]=__float_as_uint(tf32r(Xf[m*68+kb]));
            a[mt][1]=__float_as_uint(tf32r(Xf[(m+8)*68+kb]));
            a[mt][2]=__float_as_uint(tf32r(Xf[m*68+kb+4]));
            a[mt][3]=__float_as_uint(tf32r(Xf[(m+8)*68+kb+4]));
        }
        #pragma unroll
        for(int nt=0;nt<4;nt++){
            int n = wn2 + nt*8 + grp;
            bf[nt][0]=__float_as_uint(Thx[kb*68+n]);
            bf[nt][1]=__float_as_uint(Thx[(kb+4)*68+n]);
        }
        #pragma unroll
        for(int mt=0;mt<2;mt++)
            #pragma unroll
            for(int nt=0;nt<4;nt++)
                asm volatile("mma.sync.aligned.m16n8k8.row.col.f32.tf32.tf32.f32 "
                    "{%0,%1,%2,%3}, {%4,%5,%6,%7}, {%8,%9}, {%0,%1,%2,%3};\n"
                    : "+f"(acc2[mt][nt][0]),"+f"(acc2[mt][nt][1]),"+f"(acc2[mt][nt][2]),"+f"(acc2[mt][nt][3])
                    : "r"(a[mt][0]),"r"(a[mt][1]),"r"(a[mt][2]),"r"(a[mt][3]),
                      "r"(bf[nt][0]),"r"(bf[nt][1]));
    }
    __syncthreads();                         // Sep dead -> reuse as Z
    float* Zf = (float*)(sm + EP_SEP);
    float* sAdd = (float*)(sm + EP_ADD);
    #pragma unroll
    for(int mt=0;mt<2;mt++)
        #pragma unroll
        for(int h=0;h<2;h++){
            int nl2 = wm2 + mt*16 + grp + 8*h;
            #pragma unroll
            for(int nt=0;nt<4;nt++){
                int o = wn2 + nt*8 + 2*tig;
                float xx = Xf[nl2*68 + o], xy = Xf[nl2*68 + o + 1];
                int zr = half*128 + nl2;
                Zf[zr*68 + o]   = acc2[mt][nt][2*h]   + xx + sAdd[half*64 + o];
                Zf[zr*68 + o+1] = acc2[mt][nt][2*h+1] + xy + sAdd[half*64 + o + 1];
            }
        }
    __syncthreads();
    // ---- LN: 256 rows, 2 threads/row ----
    {
        float* sG = (float*)(sm+EP_G);
        float* sBe = (float*)(sm+EP_BE);
        int row = tid>>1, oh = (tid&1)*32;
        int b3 = row>>7, nl3 = row&127;
        const float* zp = Zf + row*68 + oh;
        float4 v[8];
        float s = 0.f, q = 0.f;
        #pragma unroll
        for(int j=0;j<8;j++){
            v[j] = *(const float4*)(zp + j*4);
            s += v[j].x+v[j].y+v[j].z+v[j].w;
            q += v[j].x*v[j].x+v[j].y*v[j].y+v[j].z*v[j].z+v[j].w*v[j].w;
        }
        s += __shfl_xor_sync(0xffffffffu, s, 1);
        q += __shfl_xor_sync(0xffffffffu, q, 1);
        float m = s*(1.f/64.f);
        float rs = rsqrtf(q*(1.f/64.f) - m*m + 1e-5f);
        float* op = out_sp + ((size_t)(2*by + b3)*1024 + gm0 + nl3)*64 + oh;
        #pragma unroll
        for(int j=0;j<8;j++){
            int o = oh + j*4;
            float4 w;
            w.x = (v[j].x-m)*rs*sG[o]   + sBe[o];
            w.y = (v[j].y-m)*rs*sG[o+1] + sBe[o+1];
            w.z = (v[j].z-m)*rs*sG[o+2] + sBe[o+2];
            w.w = (v[j].w-m)*rs*sG[o+3] + sBe[o+3];
            *(float4*)(op + j*4) = w;
        }
    }
#undef ISSUE_AB
}

// ---------- launch ----------
extern "C" void kernel_launch(void* const* d_in, const int* in_sizes, int n_in,
                              void* d_out, int out_size){
    const float* X     = (const float*)d_in[0];
    const float* A     = (const float*)d_in[1];
    const float* Win   = (const float*)d_in[2];
    const float* bin   = (const float*)d_in[3];
    const float* theta = (const float*)d_in[4];
    const float* cbias = (const float*)d_in[5];
    const float* eday  = (const float*)d_in[6];
    const float* eweek = (const float*)d_in[7];
    const float* gam   = (const float*)d_in[8];
    const float* bet   = (const float*)d_in[9];
    const int*   mi    = (const int*)d_in[10];
    const int*   wi    = (const int*)d_in[11];
    float* out = (float*)d_out;

    cudaFuncSetAttribute(k_fused, cudaFuncAttributeMaxDynamicSharedMemorySize, FS_SMEM);

    k_pre1<<<1097,256>>>(A, eday, eweek, mi, wi);
    k_pre2<<<1024 + NROWS/8,256>>>(A, X, Win, bin, gam, bet, out);
    k_an2<<<128,256>>>();
    for(int it=1; it<=21; ++it)
        k_matvec<<<128,256>>>(A, it);
    k_fused<<<dim3(8,288),512,FS_SMEM>>>(theta, cbias, gam, bet, out + NELEM);
}

// round 16
// speedup vs baseline: 1.1226x; 1.0690x over previous
#include <cuda_runtime.h>
#include <cuda_fp16.h>
#include <stdint.h>
#include <math.h>

#define Tdim 288
#define BT 576
#define NROWS (BT*1024)
#define NELEM ((size_t)NROWS*64)

__device__ float  g_Xp[NELEM];
__device__ __align__(16) __half g_Xph[NELEM];
__device__ float  g_L[1024*1024];                 // tf32 An
__device__ __align__(16) __half g_Lh[2048*1024];  // fp16 [An ; An^2]
__device__ float  g_dis[1024];
__device__ float  g_v[2][1024];
__device__ float  g_ss[24];
__device__ float  g_lam;
__device__ float  g_temp[Tdim*64];
__device__ float  g_ep[Tdim*64];

__device__ __forceinline__ float blockReduceSum(float v){
    __shared__ float sh[32];
    int lane = threadIdx.x & 31, wid = threadIdx.x >> 5;
    #pragma unroll
    for(int o=16;o;o>>=1) v += __shfl_down_sync(0xffffffffu, v, o);
    if(lane==0) sh[wid]=v;
    __syncthreads();
    int nw = blockDim.x >> 5;
    v = (threadIdx.x < nw) ? sh[threadIdx.x] : 0.f;
    if(wid==0){
        #pragma unroll
        for(int o=16;o;o>>=1) v += __shfl_down_sync(0xffffffffu, v, o);
    }
    return v;
}
__device__ __forceinline__ float tf32r(float f){
    uint32_t r; asm("cvt.rna.tf32.f32 %0, %1;" : "=r"(r) : "f"(f));
    return __uint_as_float(r);
}
__device__ __forceinline__ void threefry(uint32_t k0,uint32_t k1,uint32_t&x0,uint32_t&x1){
    uint32_t ks2 = k0^k1^0x1BD11BDAu;
    x0+=k0; x1+=k1;
    x0+=x1; x1=(x1<<13)|(x1>>19); x1^=x0;
    x0+=x1; x1=(x1<<15)|(x1>>17); x1^=x0;
    x0+=x1; x1=(x1<<26)|(x1>> 6); x1^=x0;
    x0+=x1; x1=(x1<< 6)|(x1>>26); x1^=x0;
    x0+=k1; x1+=ks2+1u;
    x0+=x1; x1=(x1<<17)|(x1>>15); x1^=x0;
    x0+=x1; x1=(x1<<29)|(x1>> 3); x1^=x0;
    x0+=x1; x1=(x1<<16)|(x1>>16); x1^=x0;
    x0+=x1; x1=(x1<<24)|(x1>> 8); x1^=x0;
    x0+=ks2; x1+=k0+2u;
    x0+=x1; x1=(x1<<13)|(x1>>19); x1^=x0;
    x0+=x1; x1=(x1<<15)|(x1>>17); x1^=x0;
    x0+=x1; x1=(x1<<26)|(x1>> 6); x1^=x0;
    x0+=x1; x1=(x1<< 6)|(x1>>26); x1^=x0;
    x0+=k0; x1+=k1+3u;
    x0+=x1; x1=(x1<<17)|(x1>>15); x1^=x0;
    x0+=x1; x1=(x1<<29)|(x1>> 3); x1^=x0;
    x0+=x1; x1=(x1<<16)|(x1>>16); x1^=x0;
    x0+=x1; x1=(x1<<24)|(x1>> 8); x1^=x0;
    x0+=k1; x1+=ks2+4u;
    x0+=x1; x1=(x1<<13)|(x1>>19); x1^=x0;
    x0+=x1; x1=(x1<<15)|(x1>>17); x1^=x0;
    x0+=x1; x1=(x1<<26)|(x1>> 6); x1^=x0;
    x0+=x1; x1=(x1<< 6)|(x1>>26); x1^=x0;
    x0+=ks2; x1+=k0+5u;
}
__device__ float erfinv_f(float x){
    float w = -log1pf(-x*x);
    float p;
    if (w < 5.0f){
        w -= 2.5f;
        p = 2.81022636e-08f;
        p = fmaf(p,w, 3.43273939e-07f);
        p = fmaf(p,w,-3.5233877e-06f);
        p = fmaf(p,w,-4.39150654e-06f);
        p = fmaf(p,w, 0.00021858087f);
        p = fmaf(p,w,-0.00125372503f);
        p = fmaf(p,w,-0.00417768164f);
        p = fmaf(p,w, 0.246640727f);
        p = fmaf(p,w, 1.50140941f);
    } else {
        w = sqrtf(w) - 3.0f;
        p = -0.000200214257f;
        p = fmaf(p,w, 0.000100950558f);
        p = fmaf(p,w, 0.00134934322f);
        p = fmaf(p,w,-0.00367342844f);
        p = fmaf(p,w, 0.00573950773f);
        p = fmaf(p,w,-0.0076224613f);
        p = fmaf(p,w, 0.00943887047f);
        p = fmaf(p,w, 1.00167406f);
        p = fmaf(p,w, 2.83297682f);
    }
    return p*x;
}
__device__ __forceinline__ float bits_to_normal(uint32_t bits){
    float u = __uint_as_float((bits>>9) | 0x3f800000u) - 1.0f;
    const float lo = -0.99999994f;
    float val = u*2.0f + lo;
    val = fmaxf(val, lo);
    return 1.41421354f * erfinv_f(val);
}

// ---------- launch 1: dis + init_v + temp ----------
__global__ void k_pre1(const float* __restrict__ A,
                       const float* __restrict__ eday, const float* __restrict__ eweek,
                       const int* __restrict__ mi, const int* __restrict__ wi){
    int b = blockIdx.x;
    if(b < 1024){
        float s = 0.f;
        const float* row = A + (size_t)b*1024;
        for(int j=threadIdx.x;j<1024;j+=256) s += row[j];
        s = blockReduceSum(s);
        if(threadIdx.x==0) g_dis[b] = rsqrtf(s + 1e-12f);
    } else if(b == 1024){
        if(threadIdx.x < 24) g_ss[threadIdx.x] = 0.f;
        if(threadIdx.x == 0) g_lam = 0.f;
        float loc = 0.f;
        #pragma unroll
        for(int c=0;c<4;c++){
            int i = threadIdx.x*4 + c;
            uint32_t x0 = 0u, x1 = (uint32_t)i;
            threefry(0u, 42u, x0, x1);
            float a = bits_to_normal(x0 ^ x1);
            g_v[0][i] = a;
            loc += a*a;
        }
        float ss = blockReduceSum(loc);
        if(threadIdx.x==0) g_ss[0] = ss;
    } else {
        int t = (b-1025)*4 + (threadIdx.x>>6);
        int d = threadIdx.x & 63;
        int md = ((mi[t] % 288) + 288) % 288;
        int wd = ((wi[t] % 7) + 7) % 7;
        const float factor = (float)(-9.210340371976184/64.0);
        float divv = expf((float)(d & ~1) * factor);
        float ang = (float)t * divv;
        float pe = (d & 1) ? cosf(ang) : sinf(ang);
        g_ep[t*64+d]   = pe;
        g_temp[t*64+d] = eday[md*64+d] + eweek[wd*64+d] + pe;
    }
}

// ---------- launch 2 (s0): blocks 0..1023 An prep; blocks 1024.. Xp(+fp16) + X_te ----------
__global__ void k_pre2(const float* __restrict__ A,
                       const float* __restrict__ X, const float* __restrict__ Win,
                       const float* __restrict__ bin, const float* __restrict__ gam,
                       const float* __restrict__ bet, float* __restrict__ out_te){
    __shared__ float Ws[192], bs[64], gs[64], bes[64];
    int tid = threadIdx.x;
    if(blockIdx.x < 1024){
        int i = blockIdx.x;
        float di = g_dis[i];
        for(int j=tid;j<1024;j+=256){
            float v = di * A[(size_t)i*1024+j] * g_dis[j];
            g_L[(size_t)i*1024+j]  = tf32r(v);
            g_Lh[(size_t)i*1024+j] = __float2half(v);
        }
        return;
    }
    if(tid < 192) Ws[tid] = Win[tid];
    else { int d = tid - 192; bs[d]=bin[d]; gs[d]=gam[d]; bes[d]=bet[d]; }
    __syncthreads();
    int r = (blockIdx.x-1024)*8 + (tid>>5);
    int lane = tid & 31;
    int t = (r >> 10) % Tdim;
    const float* xr = X + (size_t)r*3;
    float x0 = xr[0], x1 = xr[1], x2 = xr[2];
    int dA = lane, dB = lane + 32;
    float xpa = fmaf(x2, Ws[128+dA], fmaf(x1, Ws[64+dA], x0*Ws[dA])) + bs[dA];
    float xpb = fmaf(x2, Ws[128+dB], fmaf(x1, Ws[64+dB], x0*Ws[dB])) + bs[dB];
    size_t base = (size_t)r*64;
    g_Xp[base+dA] = xpa;
    g_Xp[base+dB] = xpb;
    g_Xph[base+dA] = __float2half(xpa);
    g_Xph[base+dB] = __float2half(xpb);
    float za = xpa + g_temp[t*64+dA];
    float zb = xpb + g_temp[t*64+dB];
    float s = za+zb, q = za*za + zb*zb;
    #pragma unroll
    for(int o=16;o;o>>=1){ s += __shfl_xor_sync(0xffffffffu,s,o); q += __shfl_xor_sync(0xffffffffu,q,o); }
    float m = s*(1.f/64.f);
    float var = q*(1.f/64.f) - m*m;
    float rs = rsqrtf(var + 1e-5f);
    out_te[base+dA] = (za-m)*rs*gs[dA] + bes[dA];
    out_te[base+dB] = (zb-m)*rs*gs[dB] + bes[dB];
}

// ---------- launch 3 (s0): An2 = An@An (tf32), fp16 out rows 1024+ ----------
__global__ void __launch_bounds__(256) k_an2(){
    __shared__ float As[128][20];
    __shared__ float Bs[16][72];
    int m0 = (blockIdx.x&7)*128, n0 = (blockIdx.x>>3)*64;
    int tid = threadIdx.x, warp = tid>>5, lane = tid&31, grp = lane>>2, tig = lane&3;
    int wm = (warp&3)*32, wn = (warp>>2)*32;
    float acc[2][4][4];
    #pragma unroll
    for(int a=0;a<2;a++)
        #pragma unroll
        for(int b=0;b<4;b++)
            #pragma unroll
            for(int c=0;c<4;c++) acc[a][b][c]=0.f;
    for(int k0=0;k0<1024;k0+=16){
        #pragma unroll
        for(int c=0;c<2;c++){
            int q = tid + 256*c; int row = q>>2, kc = (q&3)*4;
            *(float4*)&As[row][kc] = *(const float4*)&g_L[(size_t)(m0+row)*1024 + k0 + kc];
        }
        { int kk = tid>>4, d = (tid&15)*4;
          *(float4*)&Bs[kk][d] = *(const float4*)&g_L[(size_t)(k0+kk)*1024 + n0 + d]; }
        __syncthreads();
        #pragma unroll
        for(int ks=0;ks<2;ks++){
            int kb = ks*8 + tig;
            uint32_t a[2][4], bf[4][2];
            #pragma unroll
            for(int mt=0;mt<2;mt++){
                int m = wm + mt*16 + grp;
                a[mt][0]=__float_as_uint(As[m  ][kb  ]);
                a[mt][1]=__float_as_uint(As[m+8][kb  ]);
                a[mt][2]=__float_as_uint(As[m  ][kb+4]);
                a[mt][3]=__float_as_uint(As[m+8][kb+4]);
            }
            #pragma unroll
            for(int nt=0;nt<4;nt++){
                int n = wn + nt*8 + grp;
                bf[nt][0]=__float_as_uint(Bs[kb  ][n]);
                bf[nt][1]=__float_as_uint(Bs[kb+4][n]);
            }
            #pragma unroll
            for(int mt=0;mt<2;mt++)
                #pragma unroll
                for(int nt=0;nt<4;nt++)
                    asm volatile("mma.sync.aligned.m16n8k8.row.col.f32.tf32.tf32.f32 "
                        "{%0,%1,%2,%3}, {%4,%5,%6,%7}, {%8,%9}, {%0,%1,%2,%3};\n"
                        : "+f"(acc[mt][nt][0]),"+f"(acc[mt][nt][1]),"+f"(acc[mt][nt][2]),"+f"(acc[mt][nt][3])
                        : "r"(a[mt][0]),"r"(a[mt][1]),"r"(a[mt][2]),"r"(a[mt][3]),
                          "r"(bf[nt][0]),"r"(bf[nt][1]));
        }
        __syncthreads();
    }
    #pragma unroll
    for(int mt=0;mt<2;mt++)
        #pragma unroll
        for(int h=0;h<2;h++){
            int r = m0 + wm + mt*16 + grp + 8*h;
            #pragma unroll
            for(int nt=0;nt<4;nt++){
                int c = n0 + wn + nt*8 + 2*tig;
                __half2 hv = __floats2half2_rn(acc[mt][nt][2*h], acc[mt][nt][2*h+1]);
                *(uint32_t*)&g_Lh[(size_t)(1024+r)*1024 + c] = *(uint32_t*)&hv;
            }
        }
}

// ---------- matvec chain (stream s2, concurrent with pre2/an2) ----------
__global__ void k_matvec(const float* __restrict__ A, int it){
    int row = blockIdx.x*8 + (threadIdx.x>>5);
    int lane = threadIdx.x & 31;
    const float* vin = g_v[(it-1)&1];
    float scale = 1.0f/(sqrtf(g_ss[it-1]) + 1e-12f);
    const float* Ar = A + (size_t)row*1024;
    float s = 0.f;
    #pragma unroll
    for(int j=0;j<32;j++){
        int c = lane + 32*j;
        s += Ar[c]*g_dis[c]*vin[c];
    }
    #pragma unroll
    for(int o=16;o;o>>=1) s += __shfl_down_sync(0xffffffffu, s, o);
    if(lane==0){
        float w = scale*(vin[row] - g_dis[row]*s);
        if(it<=20){ g_v[it&1][row] = w; atomicAdd(&g_ss[it], w*w); }
        else atomicAdd(&g_lam, (vin[row]*scale)*w);
    }
}

// ---------- k_fused: S1,S2 mainloop + theta-combine + LN (R15 proven) ----------
#define FS_STG 29184
#define FS_BO  20480
#define EP_SEP 0
#define EP_XPS 69632
#define EP_THS 139264
#define EP_THX 157696
#define EP_ADD 175104
#define EP_G   175616
#define EP_BE  175872
#define FS_SMEM 176128
__global__ void __launch_bounds__(512,1) k_fused(const float* __restrict__ theta,
                    const float* __restrict__ cbias, const float* __restrict__ gam,
                    const float* __restrict__ bet, float* __restrict__ out_sp){
    extern __shared__ char sm[];
    uint32_t sb = (uint32_t)__cvta_generic_to_shared(sm);
    int tid = threadIdx.x, warp = tid>>5, lane = tid&31;
    int grp = lane>>2, tig = lane&3;
    int bx = blockIdx.x, by = blockIdx.y;
    int gm0 = bx*128;
    const __half* XpB = g_Xph + (size_t)(2*by)*65536;
    int wm = (warp&3)*64, wn = (warp>>2)*32;

    {
        float lam = fminf(fmaxf(g_lam,1e-6f),2.0f);
        float c2 = 2.0f/lam, c1 = c2 - 1.0f;
        #pragma unroll
        for(int c=0;c<8;c++){
            int idx = tid + 512*c;
            float t0 = theta[idx], t1 = theta[4096+idx], t2 = theta[8192+idx];
            int k = idx>>6, o = idx&63;
            *(__half*)(sm + EP_THS + k*144 + o*2)      = __float2half(-c2*t1 - 4.0f*c1*c2*t2);
            *(__half*)(sm + EP_THS + (64+k)*144 + o*2) = __float2half(2.0f*c2*c2*t2);
            *(float*)(sm + EP_THX + k*272 + o*4)       = tf32r(t0 + c1*t1 + (2.0f*c1*c1 - 1.0f)*t2);
        }
        if(tid < 128){
            int b = tid>>6, o = tid&63;
            ((float*)(sm+EP_ADD))[tid] = cbias[o] + g_ep[((2*by+b)%Tdim)*64 + o];
        }
        if(tid < 64){
            ((float*)(sm+EP_G))[tid]  = gam[tid];
            ((float*)(sm+EP_BE))[tid] = bet[tid];
        }
    }

    float acc[4][4][4];
    #pragma unroll
    for(int a=0;a<4;a++)
        #pragma unroll
        for(int b=0;b<4;b++)
            #pragma unroll
            for(int c=0;c<4;c++) acc[a][b][c]=0.f;

    int a_row = tid>>2, a_part = tid&3;
    int b_k = tid>>4, b_part = tid&15;
    size_t b_src_off = (size_t)(b_part>>3)*65536 + (size_t)b_k*64 + (b_part&7)*8;

#define ISSUE_AB(I) do{ int _i=(I); if(_i<32){ \
    uint32_t st = sb + (_i&3)*FS_STG; \
    uint32_t d0 = st + a_row*80 + a_part*16; \
    const __half* s0 = g_Lh + (size_t)(gm0+a_row)*1024 + _i*32 + a_part*8; \
    asm volatile("cp.async.cg.shared.global [%0], [%1], 16;\n"::"r"(d0),"l"(s0)); \
    const __half* s1 = g_Lh + (size_t)(1024+gm0+a_row)*1024 + _i*32 + a_part*8; \
    asm volatile("cp.async.cg.shared.global [%0], [%1], 16;\n"::"r"(d0+128*80),"l"(s1)); \
    uint32_t db = st + FS_BO + b_k*272 + b_part*16; \
    const __half* sbp = XpB + b_src_off + (size_t)(_i*32)*64; \
    asm volatile("cp.async.cg.shared.global [%0], [%1], 16;\n"::"r"(db),"l"(sbp)); } \
    asm volatile("cp.async.commit_group;\n"); }while(0)

    ISSUE_AB(0); ISSUE_AB(1); ISSUE_AB(2);

    for(int i=0;i<32;i++){
        asm volatile("cp.async.wait_group 2;\n");
        __syncthreads();
        ISSUE_AB(i+3);
        uint32_t Au = sb + (i&3)*FS_STG;
        uint32_t Bu = Au + FS_BO;
        #pragma unroll
        for(int ks=0;ks<2;ks++){
            uint32_t bf[4][2];
            #pragma unroll
            for(int nt=0;nt<4;nt++){
                uint32_t ad = Bu + (ks*16 + (lane&15))*272 + (wn + nt*8)*2;
                asm volatile("ldmatrix.sync.aligned.m8n8.x2.trans.shared.b16 {%0,%1}, [%2];\n"
                             : "=r"(bf[nt][0]), "=r"(bf[nt][1]) : "r"(ad));
            }
            #pragma unroll
            for(int mt=0;mt<4;mt++){
                uint32_t a0,a1,a2,a3;
                uint32_t ad = Au + (wm + mt*16 + ((lane>>3)&1)*8 + (lane&7))*80
                              + (ks*16 + (lane>>4)*8)*2;
                asm volatile("ldmatrix.sync.aligned.m8n8.x4.shared.b16 {%0,%1,%2,%3}, [%4];\n"
                             : "=r"(a0),"=r"(a1),"=r"(a2),"=r"(a3) : "r"(ad));
                #pragma unroll
                for(int nt=0;nt<4;nt++)
                    asm volatile("mma.sync.aligned.m16n8k16.row.col.f32.f16.f16.f32 "
                        "{%0,%1,%2,%3}, {%4,%5,%6,%7}, {%8,%9}, {%0,%1,%2,%3};\n"
                        : "+f"(acc[mt][nt][0]),"+f"(acc[mt][nt][1]),"+f"(acc[mt][nt][2]),"+f"(acc[mt][nt][3])
                        : "r"(a0),"r"(a1),"r"(a2),"r"(a3),"r"(bf[nt][0]),"r"(bf[nt][1]));
            }
        }
    }
    asm volatile("cp.async.wait_group 0;\n");
    __syncthreads();

    #pragma unroll
    for(int mt=0;mt<4;mt++)
        #pragma unroll
        for(int h=0;h<2;h++){
            int r = wm + mt*16 + grp + 8*h;
            int nl = r & 127, sb2 = r >> 7;
            #pragma unroll
            for(int nt=0;nt<4;nt++){
                int c = wn + nt*8 + 2*tig;
                int b = c >> 6, k = sb2*64 + (c & 63);
                __half2 hv = __floats2half2_rn(acc[mt][nt][2*h], acc[mt][nt][2*h+1]);
                *(uint32_t*)(sm + EP_SEP + b*34816 + nl*272 + k*2) = *(uint32_t*)&hv;
            }
        }
    #pragma unroll
    for(int c=0;c<8;c++){
        int idx = tid + 512*c;
        int row = idx>>4, part = idx&15;
        uint32_t d = sb + EP_XPS + row*272 + part*16;
        const float* s = g_Xp + ((size_t)(2*by + (row>>7))*1024 + gm0 + (row&127))*64 + part*4;
        asm volatile("cp.async.cg.shared.global [%0], [%1], 16;\n"::"r"(d),"l"(s));
    }
    asm volatile("cp.async.commit_group;\ncp.async.wait_group 0;\n");
    __syncthreads();

    int half = warp>>3, hw = warp&7;
    int wm2 = (hw&3)*32, wn2 = (hw>>2)*32;
    uint32_t SepB = sb + EP_SEP + half*34816;
    float* Xf  = (float*)(sm + EP_XPS) + half*128*68;
    float* Thx = (float*)(sm + EP_THX);
    float acc2[2][4][4];
    #pragma unroll
    for(int a=0;a<2;a++)
        #pragma unroll
        for(int b=0;b<4;b++)
            #pragma unroll
            for(int c=0;c<4;c++) acc2[a][b][c]=0.f;

    #pragma unroll
    for(int ks=0;ks<8;ks++){
        uint32_t bf[4][2];
        #pragma unroll
        for(int nt=0;nt<4;nt++){
            uint32_t ad = sb + EP_THS + (ks*16 + (lane&15))*144 + (wn2 + nt*8)*2;
            asm volatile("ldmatrix.sync.aligned.m8n8.x2.trans.shared.b16 {%0,%1}, [%2];\n"
                         : "=r"(bf[nt][0]), "=r"(bf[nt][1]) : "r"(ad));
        }
        #pragma unroll
        for(int mt=0;mt<2;mt++){
            uint32_t a0,a1,a2,a3;
            uint32_t ad = SepB + (wm2 + mt*16 + ((lane>>3)&1)*8 + (lane&7))*272
                          + (ks*16 + (lane>>4)*8)*2;
            asm volatile("ldmatrix.sync.aligned.m8n8.x4.shared.b16 {%0,%1,%2,%3}, [%4];\n"
                         : "=r"(a0),"=r"(a1),"=r"(a2),"=r"(a3) : "r"(ad));
            #pragma unroll
            for(int nt=0;nt<4;nt++)
                asm volatile("mma.sync.aligned.m16n8k16.row.col.f32.f16.f16.f32 "
                    "{%0,%1,%2,%3}, {%4,%5,%6,%7}, {%8,%9}, {%0,%1,%2,%3};\n"
                    : "+f"(acc2[mt][nt][0]),"+f"(acc2[mt][nt][1]),"+f"(acc2[mt][nt][2]),"+f"(acc2[mt][nt][3])
                    : "r"(a0),"r"(a1),"r"(a2),"r"(a3),"r"(bf[nt][0]),"r"(bf[nt][1]));
        }
    }
    #pragma unroll
    for(int ks=0;ks<8;ks++){
        int kb = ks*8 + tig;
        uint32_t a[2][4], bf[4][2];
        #pragma unroll
        for(int mt=0;mt<2;mt++){
            int m = wm2 + mt*16 + grp;
            a[mt][0]=__float_as_uint(tf32r(Xf[m*68+kb]));
            a[mt][1]=__float_as_uint(tf32r(Xf[(m+8)*68+kb]));
            a[mt][2]=__float_as_uint(tf32r(Xf[m*68+kb+4]));
            a[mt][3]=__float_as_uint(tf32r(Xf[(m+8)*68+kb+4]));
        }
        #pragma unroll
        for(int nt=0;nt<4;nt++){
            int n = wn2 + nt*8 + grp;
            bf[nt][0]=__float_as_uint(Thx[kb*68+n]);
            bf[nt][1]=__float_as_uint(Thx[(kb+4)*68+n]);
        }
        #pragma unroll
        for(int mt=0;mt<2;mt++)
            #pragma unroll
            for(int nt=0;nt<4;nt++)
                asm volatile("mma.sync.aligned.m16n8k8.row.col.f32.tf32.tf32.f32 "
                    "{%0,%1,%2,%3}, {%4,%5,%6,%7}, {%8,%9}, {%0,%1,%2,%3};\n"
                    : "+f"(acc2[mt][nt][0]),"+f"(acc2[mt][nt][1]),"+f"(acc2[mt][nt][2]),"+f"(acc2[mt][nt][3])
                    : "r"(a[mt][0]),"r"(a[mt][1]),"r"(a[mt][2]),"r"(a[mt][3]),
                      "r"(bf[nt][0]),"r"(bf[nt][1]));
    }
    __syncthreads();
    float* Zf = (float*)(sm + EP_SEP);
    float* sAdd = (float*)(sm + EP_ADD);
    #pragma unroll
    for(int mt=0;mt<2;mt++)
        #pragma unroll
        for(int h=0;h<2;h++){
            int nl2 = wm2 + mt*16 + grp + 8*h;
            #pragma unroll
            for(int nt=0;nt<4;nt++){
                int o = wn2 + nt*8 + 2*tig;
                float xx = Xf[nl2*68 + o], xy = Xf[nl2*68 + o + 1];
                int zr = half*128 + nl2;
                Zf[zr*68 + o]   = acc2[mt][nt][2*h]   + xx + sAdd[half*64 + o];
                Zf[zr*68 + o+1] = acc2[mt][nt][2*h+1] + xy + sAdd[half*64 + o + 1];
            }
        }
    __syncthreads();
    {
        float* sG = (float*)(sm+EP_G);
        float* sBe = (float*)(sm+EP_BE);
        int row = tid>>1, oh = (tid&1)*32;
        int b3 = row>>7, nl3 = row&127;
        const float* zp = Zf + row*68 + oh;
        float4 v[8];
        float s = 0.f, q = 0.f;
        #pragma unroll
        for(int j=0;j<8;j++){
            v[j] = *(const float4*)(zp + j*4);
            s += v[j].x+v[j].y+v[j].z+v[j].w;
            q += v[j].x*v[j].x+v[j].y*v[j].y+v[j].z*v[j].z+v[j].w*v[j].w;
        }
        s += __shfl_xor_sync(0xffffffffu, s, 1);
        q += __shfl_xor_sync(0xffffffffu, q, 1);
        float m = s*(1.f/64.f);
        float rs = rsqrtf(q*(1.f/64.f) - m*m + 1e-5f);
        float* op = out_sp + ((size_t)(2*by + b3)*1024 + gm0 + nl3)*64 + oh;
        #pragma unroll
        for(int j=0;j<8;j++){
            int o = oh + j*4;
            float4 w;
            w.x = (v[j].x-m)*rs*sG[o]   + sBe[o];
            w.y = (v[j].y-m)*rs*sG[o+1] + sBe[o+1];
            w.z = (v[j].z-m)*rs*sG[o+2] + sBe[o+2];
            w.w = (v[j].w-m)*rs*sG[o+3] + sBe[o+3];
            *(float4*)(op + j*4) = w;
        }
    }
#undef ISSUE_AB
}

// ---------- launch ----------
extern "C" void kernel_launch(void* const* d_in, const int* in_sizes, int n_in,
                              void* d_out, int out_size){
    const float* X     = (const float*)d_in[0];
    const float* A     = (const float*)d_in[1];
    const float* Win   = (const float*)d_in[2];
    const float* bin   = (const float*)d_in[3];
    const float* theta = (const float*)d_in[4];
    const float* cbias = (const float*)d_in[5];
    const float* eday  = (const float*)d_in[6];
    const float* eweek = (const float*)d_in[7];
    const float* gam   = (const float*)d_in[8];
    const float* bet   = (const float*)d_in[9];
    const int*   mi    = (const int*)d_in[10];
    const int*   wi    = (const int*)d_in[11];
    float* out = (float*)d_out;

    cudaFuncSetAttribute(k_fused, cudaFuncAttributeMaxDynamicSharedMemorySize, FS_SMEM);

    // fork/join: power-iteration chain on s2 overlaps pre2 + an2 on the main stream
    cudaStream_t s2;
    cudaStreamCreateWithFlags(&s2, cudaStreamNonBlocking);
    cudaEvent_t eF, eJ;
    cudaEventCreateWithFlags(&eF, cudaEventDisableTiming);
    cudaEventCreateWithFlags(&eJ, cudaEventDisableTiming);

    k_pre1<<<1097,256>>>(A, eday, eweek, mi, wi);
    cudaEventRecord(eF, 0);
    cudaStreamWaitEvent(s2, eF, 0);
    for(int it=1; it<=21; ++it)
        k_matvec<<<128,256,0,s2>>>(A, it);
    cudaEventRecord(eJ, s2);

    k_pre2<<<1024 + NROWS/8,256>>>(A, X, Win, bin, gam, bet, out);
    k_an2<<<128,256>>>();
    cudaStreamWaitEvent(0, eJ, 0);
    k_fused<<<dim3(8,288),512,FS_SMEM>>>(theta, cbias, gam, bet, out + NELEM);
    // s2/eF/eJ intentionally not destroyed: destruction during active graph
    // capture is unsafe; kernel_launch runs only a handful of times.
}